// round 2
// baseline (speedup 1.0000x reference)
#include <cuda_runtime.h>
#include <cuda_bf16.h>
#include <math.h>

// ---------------- problem constants ----------------
#define B_      2
#define S_      1024
#define ROWS_   (B_ * S_)        // 2048
#define HDIM_   1024
#define NH_     16
#define HD_     64
#define NL_     8
#define FF_     4096
#define INDIM_  1280
#define LREL_   257
#define NCLS_   100
#define NEGV   -1000000000.0f

// ---------------- scratch (allocation-free) ----------------
__device__ float g_zin[ROWS_ * INDIM_];
__device__ float g_z  [ROWS_ * HDIM_];
__device__ float g_h  [ROWS_ * HDIM_];
__device__ float g_qkv[ROWS_ * 3 * HDIM_];
__device__ float g_o  [ROWS_ * HDIM_];
__device__ float g_f  [ROWS_ * FF_];

// ---------------- LayerNorm: one block per row ----------------
__global__ void __launch_bounds__(256) ln_kernel(const float* __restrict__ in,
                                                 const float* __restrict__ g,
                                                 const float* __restrict__ b,
                                                 float* __restrict__ out,
                                                 int D, float eps) {
    int row = blockIdx.x;
    const float* p = in + (size_t)row * D;
    float s = 0.f, sq = 0.f;
    for (int i = threadIdx.x; i < D; i += 256) {
        float v = p[i];
        s += v; sq += v * v;
    }
    #pragma unroll
    for (int o = 16; o > 0; o >>= 1) {
        s  += __shfl_xor_sync(0xffffffffu, s,  o);
        sq += __shfl_xor_sync(0xffffffffu, sq, o);
    }
    __shared__ float ss[8], ssq[8];
    __shared__ float sm_mean, sm_rstd;
    int w = threadIdx.x >> 5;
    if ((threadIdx.x & 31) == 0) { ss[w] = s; ssq[w] = sq; }
    __syncthreads();
    if (threadIdx.x == 0) {
        float S = 0.f, SQ = 0.f;
        #pragma unroll
        for (int i = 0; i < 8; i++) { S += ss[i]; SQ += ssq[i]; }
        float mean = S / D;
        float var  = SQ / D - mean * mean;
        sm_mean = mean;
        sm_rstd = rsqrtf(var + eps);
    }
    __syncthreads();
    float mean = sm_mean, rstd = sm_rstd;
    float* q = out + (size_t)row * D;
    for (int i = threadIdx.x; i < D; i += 256)
        q[i] = (p[i] - mean) * rstd * g[i] + b[i];
}

// ---------------- generic NT GEMM: C(M,N) = A(M,K) @ W(N,K)^T (+epilogue) ----------
// EPI: 0 = +bias, 1 = gelu(+bias), 2 = residual + (+bias)
#define TM 64
#define TN 64
#define TK 16

template <int EPI>
__global__ void __launch_bounds__(256) gemm_nt(const float* __restrict__ A,
                                               const float* __restrict__ W,
                                               const float* __restrict__ bias,
                                               const float* __restrict__ res,
                                               float* __restrict__ C,
                                               int M, int N, int K) {
    __shared__ float As[TK][TM + 1];
    __shared__ float Ws[TK][TN + 1];
    int tid = threadIdx.x;
    int tx = tid & 15, ty = tid >> 4;
    int m0 = blockIdx.y * TM;
    int n0 = blockIdx.x * TN;
    int lr = tid >> 4;   // 0..15
    int lk = tid & 15;   // 0..15

    float acc[4][4] = {};

    for (int k0 = 0; k0 < K; k0 += TK) {
        #pragma unroll
        for (int rr = 0; rr < 4; rr++) {
            int r = lr + rr * 16;
            As[lk][r] = A[(size_t)(m0 + r) * K + k0 + lk];
            int n = n0 + r;
            Ws[lk][r] = (n < N) ? W[(size_t)n * K + k0 + lk] : 0.f;
        }
        __syncthreads();
        #pragma unroll
        for (int kk = 0; kk < TK; kk++) {
            float a[4], w[4];
            #pragma unroll
            for (int i = 0; i < 4; i++) a[i] = As[kk][ty * 4 + i];
            #pragma unroll
            for (int j = 0; j < 4; j++) w[j] = Ws[kk][tx * 4 + j];
            #pragma unroll
            for (int i = 0; i < 4; i++)
                #pragma unroll
                for (int j = 0; j < 4; j++)
                    acc[i][j] += a[i] * w[j];
        }
        __syncthreads();
    }

    #pragma unroll
    for (int i = 0; i < 4; i++) {
        int r = m0 + ty * 4 + i;
        #pragma unroll
        for (int j = 0; j < 4; j++) {
            int c = n0 + tx * 4 + j;
            if (c < N) {
                float v = acc[i][j] + bias[c];
                if (EPI == 1) {
                    v = 0.5f * v * (1.0f + erff(v * 0.70710678118654752f));
                } else if (EPI == 2) {
                    v += res[(size_t)r * N + c];
                }
                C[(size_t)r * N + c] = v;
            }
        }
    }
}

// ---------------- fused causal attention (flash-style, fp32) ----------------
// grid: (S/64, B*NH), block 256.  One block = one (b, h, q-tile of 64 rows).
#define QT 64
#define PAD 65

__global__ void __launch_bounds__(256) attn_kernel(const float* __restrict__ qkv,
                                                   const float* __restrict__ rel,
                                                   float* __restrict__ o) {
    extern __shared__ float sm[];
    float* Qs   = sm;                      // 64*65
    float* Ks   = Qs + QT * PAD;
    float* Vs   = Ks + QT * PAD;
    float* Ps   = Vs + QT * PAD;
    float* relS = Ps + QT * PAD;           // 257
    float* rowm = relS + LREL_;            // 64
    float* rowl = rowm + 64;
    float* rowsc = rowl + 64;

    int tid = threadIdx.x;
    int tx = tid & 15, ty = tid >> 4;
    int qt = blockIdx.x;
    int b  = blockIdx.y >> 4;
    int h  = blockIdx.y & 15;

    const size_t base = (size_t)b * S_ * 3 * HDIM_ + (size_t)h * HD_;

    for (int i = tid; i < LREL_; i += 256) relS[i] = rel[h * LREL_ + i];
    for (int i = tid; i < QT * HD_; i += 256) {
        int r = i >> 6, d = i & 63;
        Qs[r * PAD + d] = qkv[base + (size_t)(qt * QT + r) * (3 * HDIM_) + d];
    }
    if (tid < 64) { rowm[tid] = -INFINITY; rowl[tid] = 0.f; }

    float acc[4][4] = {};
    __syncthreads();

    const float scale = 0.125f;   // 1/sqrt(64)

    for (int kt = 0; kt <= qt; kt++) {
        for (int i = tid; i < QT * HD_; i += 256) {
            int r = i >> 6, d = i & 63;
            size_t gidx = base + (size_t)(kt * QT + r) * (3 * HDIM_) + d;
            Ks[r * PAD + d] = qkv[gidx + HDIM_];
            Vs[r * PAD + d] = qkv[gidx + 2 * HDIM_];
        }
        __syncthreads();

        // scores tile = Q @ K^T
        float s4[4][4] = {};
        #pragma unroll
        for (int d = 0; d < HD_; d++) {
            float a[4], kreg[4];
            #pragma unroll
            for (int i = 0; i < 4; i++) a[i] = Qs[(ty * 4 + i) * PAD + d];
            #pragma unroll
            for (int j = 0; j < 4; j++) kreg[j] = Ks[(tx * 4 + j) * PAD + d];
            #pragma unroll
            for (int i = 0; i < 4; i++)
                #pragma unroll
                for (int j = 0; j < 4; j++)
                    s4[i][j] += a[i] * kreg[j];
        }
        #pragma unroll
        for (int i = 0; i < 4; i++) {
            int qg = qt * QT + ty * 4 + i;
            #pragma unroll
            for (int j = 0; j < 4; j++) {
                int kg = kt * QT + tx * 4 + j;
                float v;
                if (kg > qg) {
                    v = NEGV;
                } else {
                    int idx = kg - qg;
                    if (idx < -128) idx = -128;
                    v = s4[i][j] * scale + relS[idx + 128];
                }
                Ps[(ty * 4 + i) * PAD + tx * 4 + j] = v;
            }
        }
        __syncthreads();

        // online softmax per row (threads 0..63)
        if (tid < 64) {
            int r = tid;
            float mold = rowm[r];
            float mx = mold;
            #pragma unroll 8
            for (int c = 0; c < 64; c++) mx = fmaxf(mx, Ps[r * PAD + c]);
            float sum = 0.f;
            #pragma unroll 8
            for (int c = 0; c < 64; c++) {
                float e = __expf(Ps[r * PAD + c] - mx);
                Ps[r * PAD + c] = e;
                sum += e;
            }
            float sc = __expf(mold - mx);
            rowsc[r] = sc;
            rowl[r]  = rowl[r] * sc + sum;
            rowm[r]  = mx;
        }
        __syncthreads();

        // rescale accumulators + P @ V
        #pragma unroll
        for (int i = 0; i < 4; i++) {
            float sc = rowsc[ty * 4 + i];
            #pragma unroll
            for (int j = 0; j < 4; j++) acc[i][j] *= sc;
        }
        #pragma unroll
        for (int kk = 0; kk < 64; kk++) {
            float p[4], v4[4];
            #pragma unroll
            for (int i = 0; i < 4; i++) p[i] = Ps[(ty * 4 + i) * PAD + kk];
            #pragma unroll
            for (int j = 0; j < 4; j++) v4[j] = Vs[kk * PAD + tx * 4 + j];
            #pragma unroll
            for (int i = 0; i < 4; i++)
                #pragma unroll
                for (int j = 0; j < 4; j++)
                    acc[i][j] += p[i] * v4[j];
        }
        __syncthreads();
    }

    #pragma unroll
    for (int i = 0; i < 4; i++) {
        int r = ty * 4 + i;
        float inv = 1.f / rowl[r];
        int qg = qt * QT + r;
        #pragma unroll
        for (int j = 0; j < 4; j++) {
            o[((size_t)b * S_ + qg) * HDIM_ + h * HD_ + tx * 4 + j] = acc[i][j] * inv;
        }
    }
}

#define ATTN_SMEM_BYTES ((4 * QT * PAD + LREL_ + 3 * 64) * (int)sizeof(float))

// ---------------- host orchestration ----------------
extern "C" void kernel_launch(void* const* d_in, const int* in_sizes, int n_in,
                              void* d_out, int out_size) {
    const float* x        = (const float*)d_in[0];
    const float* pe_ln1_g = (const float*)d_in[1];
    const float* pe_ln1_b = (const float*)d_in[2];
    const float* pe_w     = (const float*)d_in[3];
    const float* pe_b     = (const float*)d_in[4];
    const float* pe_ln2_g = (const float*)d_in[5];
    const float* pe_ln2_b = (const float*)d_in[6];
    const float* lnA_g    = (const float*)d_in[7];
    const float* lnA_b    = (const float*)d_in[8];
    const float* qkv_w    = (const float*)d_in[9];
    const float* qkv_b    = (const float*)d_in[10];
    const float* out_w    = (const float*)d_in[11];
    const float* out_b    = (const float*)d_in[12];
    const float* lnF_g    = (const float*)d_in[13];
    const float* lnF_b    = (const float*)d_in[14];
    const float* fc1_w    = (const float*)d_in[15];
    const float* fc1_b    = (const float*)d_in[16];
    const float* fc2_w    = (const float*)d_in[17];
    const float* fc2_b    = (const float*)d_in[18];
    const float* rel_tab  = (const float*)d_in[19];
    const float* final_g  = (const float*)d_in[20];
    const float* final_b  = (const float*)d_in[21];
    const float* head_w   = (const float*)d_in[22];
    const float* head_b   = (const float*)d_in[23];
    float* out = (float*)d_out;

    float *zin, *z, *h, *qkv, *o, *f;
    cudaGetSymbolAddress((void**)&zin, g_zin);
    cudaGetSymbolAddress((void**)&z,   g_z);
    cudaGetSymbolAddress((void**)&h,   g_h);
    cudaGetSymbolAddress((void**)&qkv, g_qkv);
    cudaGetSymbolAddress((void**)&o,   g_o);
    cudaGetSymbolAddress((void**)&f,   g_f);

    cudaFuncSetAttribute(attn_kernel,
                         cudaFuncAttributeMaxDynamicSharedMemorySize,
                         ATTN_SMEM_BYTES);

    // patch embed: LN(1280) -> GEMM -> LN(1024)
    ln_kernel<<<ROWS_, 256>>>(x, pe_ln1_g, pe_ln1_b, zin, INDIM_, 1e-6f);
    gemm_nt<0><<<dim3(HDIM_ / TN, ROWS_ / TM), 256>>>(zin, pe_w, pe_b, nullptr, h,
                                                      ROWS_, HDIM_, INDIM_);
    ln_kernel<<<ROWS_, 256>>>(h, pe_ln2_g, pe_ln2_b, z, HDIM_, 1e-6f);

    for (int l = 0; l < NL_; l++) {
        const float* qw = qkv_w + (size_t)l * 3 * HDIM_ * HDIM_;
        const float* qb = qkv_b + (size_t)l * 3 * HDIM_;
        const float* ow = out_w + (size_t)l * HDIM_ * HDIM_;
        const float* ob = out_b + (size_t)l * HDIM_;
        const float* f1w = fc1_w + (size_t)l * FF_ * HDIM_;
        const float* f1b = fc1_b + (size_t)l * FF_;
        const float* f2w = fc2_w + (size_t)l * HDIM_ * FF_;
        const float* f2b = fc2_b + (size_t)l * HDIM_;

        ln_kernel<<<ROWS_, 256>>>(z, lnA_g + l * HDIM_, lnA_b + l * HDIM_, h, HDIM_, 1e-5f);
        gemm_nt<0><<<dim3(3 * HDIM_ / TN, ROWS_ / TM), 256>>>(h, qw, qb, nullptr, qkv,
                                                              ROWS_, 3 * HDIM_, HDIM_);
        attn_kernel<<<dim3(S_ / QT, B_ * NH_), 256, ATTN_SMEM_BYTES>>>(qkv, rel_tab, o);
        gemm_nt<2><<<dim3(HDIM_ / TN, ROWS_ / TM), 256>>>(o, ow, ob, z, z,
                                                          ROWS_, HDIM_, HDIM_);
        ln_kernel<<<ROWS_, 256>>>(z, lnF_g + l * HDIM_, lnF_b + l * HDIM_, h, HDIM_, 1e-5f);
        gemm_nt<1><<<dim3(FF_ / TN, ROWS_ / TM), 256>>>(h, f1w, f1b, nullptr, f,
                                                        ROWS_, FF_, HDIM_);
        gemm_nt<2><<<dim3(HDIM_ / TN, ROWS_ / TM), 256>>>(f, f2w, f2b, z, z,
                                                          ROWS_, HDIM_, FF_);
    }

    ln_kernel<<<ROWS_, 256>>>(z, final_g, final_b, h, HDIM_, 1e-5f);
    gemm_nt<0><<<dim3((NCLS_ + TN - 1) / TN, ROWS_ / TM), 256>>>(h, head_w, head_b, nullptr,
                                                                 out, ROWS_, NCLS_, HDIM_);
}

// round 4
// speedup vs baseline: 3.0573x; 3.0573x over previous
#include <cuda_runtime.h>
#include <cuda_bf16.h>
#include <math.h>
#include <stdint.h>

// ---------------- problem constants ----------------
#define B_      2
#define S_      1024
#define ROWS_   (B_ * S_)        // 2048
#define HDIM_   1024
#define NH_     16
#define HD_     64
#define NL_     8
#define FF_     4096
#define INDIM_  1280
#define LREL_   257
#define NCLS_   100
#define NEGV   -1000000000.0f

// ---------------- scratch (allocation-free) ----------------
__device__ float g_zin[ROWS_ * INDIM_];
__device__ float g_z  [ROWS_ * HDIM_];
__device__ float g_h  [ROWS_ * HDIM_];
__device__ float g_qkv[ROWS_ * 3 * HDIM_];
__device__ float g_o  [ROWS_ * HDIM_];
__device__ float g_f  [ROWS_ * FF_];

// ---------------- LayerNorm: one block per row ----------------
__global__ void __launch_bounds__(256) ln_kernel(const float* __restrict__ in,
                                                 const float* __restrict__ g,
                                                 const float* __restrict__ b,
                                                 float* __restrict__ out,
                                                 int D, float eps) {
    int row = blockIdx.x;
    const float* p = in + (size_t)row * D;
    float s = 0.f, sq = 0.f;
    for (int i = threadIdx.x; i < D; i += 256) {
        float v = p[i];
        s += v; sq += v * v;
    }
    #pragma unroll
    for (int o = 16; o > 0; o >>= 1) {
        s  += __shfl_xor_sync(0xffffffffu, s,  o);
        sq += __shfl_xor_sync(0xffffffffu, sq, o);
    }
    __shared__ float ss[8], ssq[8];
    __shared__ float sm_mean, sm_rstd;
    int w = threadIdx.x >> 5;
    if ((threadIdx.x & 31) == 0) { ss[w] = s; ssq[w] = sq; }
    __syncthreads();
    if (threadIdx.x == 0) {
        float S = 0.f, SQ = 0.f;
        #pragma unroll
        for (int i = 0; i < 8; i++) { S += ss[i]; SQ += ssq[i]; }
        float mean = S / D;
        float var  = SQ / D - mean * mean;
        sm_mean = mean;
        sm_rstd = rsqrtf(var + eps);
    }
    __syncthreads();
    float mean = sm_mean, rstd = sm_rstd;
    float* q = out + (size_t)row * D;
    for (int i = threadIdx.x; i < D; i += 256)
        q[i] = (p[i] - mean) * rstd * g[i] + b[i];
}

// ---------------- TF32 tensor-core NT GEMM ----------------
// C(M,N) = A(M,K) @ W(N,K)^T + epilogue
// EPI: 0 = +bias, 1 = gelu(+bias), 2 = residual + (+bias)
#define BM 128
#define BN 128
#define BK 16
#define SA 136   // smem k-row stride in floats (128 + 8 pad)

__device__ __forceinline__ uint32_t f2tf(float f) {
    uint32_t u;
    asm("cvt.rna.tf32.f32 %0, %1;" : "=r"(u) : "f"(f));
    return u;
}

__device__ __forceinline__ void mma_tf32(float* c, const uint32_t* a, const uint32_t* b) {
    asm volatile("mma.sync.aligned.m16n8k8.row.col.f32.tf32.tf32.f32 "
                 "{%0,%1,%2,%3}, {%4,%5,%6,%7}, {%8,%9}, {%0,%1,%2,%3};"
                 : "+f"(c[0]), "+f"(c[1]), "+f"(c[2]), "+f"(c[3])
                 : "r"(a[0]), "r"(a[1]), "r"(a[2]), "r"(a[3]),
                   "r"(b[0]), "r"(b[1]));
}

// swizzled smem index: row k, logical column c (0..127)
__device__ __forceinline__ int sw(int k, int c) {
    return k * SA + (c ^ (((k >> 2) & 3) << 3));
}

template <int EPI>
__global__ void __launch_bounds__(256, 2) gemm_tf32(const float* __restrict__ A,
                                                    const float* __restrict__ W,
                                                    const float* __restrict__ bias,
                                                    const float* __restrict__ res,
                                                    float* __restrict__ C,
                                                    int M, int N, int K) {
    __shared__ uint32_t As[2][BK * SA];
    __shared__ uint32_t Ws[2][BK * SA];

    const int tid  = threadIdx.x;
    const int lane = tid & 31;
    const int warp = tid >> 5;
    const int wm   = (warp & 1) * 64;   // warp row offset in block tile
    const int wn   = (warp >> 1) * 32;  // warp col offset
    const int m0   = blockIdx.y * BM;
    const int n0   = blockIdx.x * BN;

    float acc[4][4][4] = {};

    // loader mapping: lin = tid + 256*i, row = lin>>2 (0..127), kq = lin&3
    const int lr0 = tid >> 2,        lq0 = (tid & 3) * 4;
    const int lr1 = (tid + 256) >> 2, lq1 = (tid & 3) * 4;  // same kq, rows 64..127
    (void)lr1; (void)lq1;

    float4 ar[2], wr[2];

    // ---- load chunk 0 straight into smem buf 0 ----
    {
        #pragma unroll
        for (int i = 0; i < 2; i++) {
            int lin = tid + 256 * i;
            int r = lin >> 2, kq = (lin & 3) * 4;
            float4 va = *(const float4*)&A[(size_t)(m0 + r) * K + kq];
            float4 vw;
            int n = n0 + r;
            if (n < N) vw = *(const float4*)&W[(size_t)n * K + kq];
            else       vw = make_float4(0.f, 0.f, 0.f, 0.f);
            As[0][sw(kq + 0, r)] = f2tf(va.x);
            As[0][sw(kq + 1, r)] = f2tf(va.y);
            As[0][sw(kq + 2, r)] = f2tf(va.z);
            As[0][sw(kq + 3, r)] = f2tf(va.w);
            Ws[0][sw(kq + 0, r)] = f2tf(vw.x);
            Ws[0][sw(kq + 1, r)] = f2tf(vw.y);
            Ws[0][sw(kq + 2, r)] = f2tf(vw.z);
            Ws[0][sw(kq + 3, r)] = f2tf(vw.w);
        }
    }
    __syncthreads();

    const int nchunks = K / BK;
    int buf = 0;
    for (int c = 0; c < nchunks; c++) {
        const bool has_next = (c + 1 < nchunks);
        const int k0n = (c + 1) * BK;
        if (has_next) {
            #pragma unroll
            for (int i = 0; i < 2; i++) {
                int lin = tid + 256 * i;
                int r = lin >> 2, kq = (lin & 3) * 4;
                ar[i] = *(const float4*)&A[(size_t)(m0 + r) * K + k0n + kq];
                int n = n0 + r;
                if (n < N) wr[i] = *(const float4*)&W[(size_t)n * K + k0n + kq];
                else       wr[i] = make_float4(0.f, 0.f, 0.f, 0.f);
            }
        }

        // ---- compute on buf ----
        const uint32_t* Ab = As[buf];
        const uint32_t* Wb = Ws[buf];
        #pragma unroll
        for (int ks = 0; ks < BK; ks += 8) {
            const int kq0 = (ks >> 2) & 3;
            const int kq1 = kq0 + 1;
            const int krow0 = ks + (lane & 3);
            const int krow1 = ks + 4 + (lane & 3);
            uint32_t af[4][4];
            #pragma unroll
            for (int mt = 0; mt < 4; mt++) {
                int mb = wm + mt * 16 + (lane >> 2);
                af[mt][0] = Ab[krow0 * SA + ( mb      ^ (kq0 << 3))];
                af[mt][1] = Ab[krow0 * SA + ((mb + 8) ^ (kq0 << 3))];
                af[mt][2] = Ab[krow1 * SA + ( mb      ^ (kq1 << 3))];
                af[mt][3] = Ab[krow1 * SA + ((mb + 8) ^ (kq1 << 3))];
            }
            uint32_t bf[4][2];
            #pragma unroll
            for (int nt = 0; nt < 4; nt++) {
                int nb = wn + nt * 8 + (lane >> 2);
                bf[nt][0] = Wb[krow0 * SA + (nb ^ (kq0 << 3))];
                bf[nt][1] = Wb[krow1 * SA + (nb ^ (kq1 << 3))];
            }
            #pragma unroll
            for (int mt = 0; mt < 4; mt++)
                #pragma unroll
                for (int nt = 0; nt < 4; nt++)
                    mma_tf32(acc[mt][nt], af[mt], bf[nt]);
        }

        if (has_next) {
            int nb = buf ^ 1;
            #pragma unroll
            for (int i = 0; i < 2; i++) {
                int lin = tid + 256 * i;
                int r = lin >> 2, kq = (lin & 3) * 4;
                As[nb][sw(kq + 0, r)] = f2tf(ar[i].x);
                As[nb][sw(kq + 1, r)] = f2tf(ar[i].y);
                As[nb][sw(kq + 2, r)] = f2tf(ar[i].z);
                As[nb][sw(kq + 3, r)] = f2tf(ar[i].w);
                Ws[nb][sw(kq + 0, r)] = f2tf(wr[i].x);
                Ws[nb][sw(kq + 1, r)] = f2tf(wr[i].y);
                Ws[nb][sw(kq + 2, r)] = f2tf(wr[i].z);
                Ws[nb][sw(kq + 3, r)] = f2tf(wr[i].w);
            }
            __syncthreads();
            buf = nb;
        }
    }

    // ---- epilogue ----
    #pragma unroll
    for (int mt = 0; mt < 4; mt++) {
        const int r0 = m0 + wm + mt * 16 + (lane >> 2);
        #pragma unroll
        for (int nt = 0; nt < 4; nt++) {
            const int c0 = n0 + wn + nt * 8 + (lane & 3) * 2;
            const float* a4 = acc[mt][nt];
            #pragma unroll
            for (int e = 0; e < 4; e++) {
                int r = r0 + (e >> 1) * 8;
                int cc = c0 + (e & 1);
                if (cc < N) {
                    float v = a4[e] + bias[cc];
                    if (EPI == 1) {
                        v = 0.5f * v * (1.0f + erff(v * 0.70710678118654752f));
                    } else if (EPI == 2) {
                        v += res[(size_t)r * N + cc];
                    }
                    C[(size_t)r * N + cc] = v;
                }
            }
        }
    }
}

// ---------------- fused causal attention (flash-style, fp32) ----------------
#define QT 64
#define PAD 65

__global__ void __launch_bounds__(256) attn_kernel(const float* __restrict__ qkv,
                                                   const float* __restrict__ rel,
                                                   float* __restrict__ o) {
    extern __shared__ float sm[];
    float* Qs   = sm;                      // 64*65
    float* Ks   = Qs + QT * PAD;
    float* Vs   = Ks + QT * PAD;
    float* Ps   = Vs + QT * PAD;
    float* relS = Ps + QT * PAD;           // 257
    float* rowm = relS + LREL_;            // 64
    float* rowl = rowm + 64;
    float* rowsc = rowl + 64;

    int tid = threadIdx.x;
    int tx = tid & 15, ty = tid >> 4;
    int qt = blockIdx.x;
    int b  = blockIdx.y >> 4;
    int h  = blockIdx.y & 15;

    const size_t base = (size_t)b * S_ * 3 * HDIM_ + (size_t)h * HD_;

    for (int i = tid; i < LREL_; i += 256) relS[i] = rel[h * LREL_ + i];
    for (int i = tid; i < QT * HD_; i += 256) {
        int r = i >> 6, d = i & 63;
        Qs[r * PAD + d] = qkv[base + (size_t)(qt * QT + r) * (3 * HDIM_) + d];
    }
    if (tid < 64) { rowm[tid] = -INFINITY; rowl[tid] = 0.f; }

    float acc[4][4] = {};
    __syncthreads();

    const float scale = 0.125f;   // 1/sqrt(64)

    for (int kt = 0; kt <= qt; kt++) {
        for (int i = tid; i < QT * HD_; i += 256) {
            int r = i >> 6, d = i & 63;
            size_t gidx = base + (size_t)(kt * QT + r) * (3 * HDIM_) + d;
            Ks[r * PAD + d] = qkv[gidx + HDIM_];
            Vs[r * PAD + d] = qkv[gidx + 2 * HDIM_];
        }
        __syncthreads();

        float s4[4][4] = {};
        #pragma unroll
        for (int d = 0; d < HD_; d++) {
            float a[4], kreg[4];
            #pragma unroll
            for (int i = 0; i < 4; i++) a[i] = Qs[(ty * 4 + i) * PAD + d];
            #pragma unroll
            for (int j = 0; j < 4; j++) kreg[j] = Ks[(tx * 4 + j) * PAD + d];
            #pragma unroll
            for (int i = 0; i < 4; i++)
                #pragma unroll
                for (int j = 0; j < 4; j++)
                    s4[i][j] += a[i] * kreg[j];
        }
        #pragma unroll
        for (int i = 0; i < 4; i++) {
            int qg = qt * QT + ty * 4 + i;
            #pragma unroll
            for (int j = 0; j < 4; j++) {
                int kg = kt * QT + tx * 4 + j;
                float v;
                if (kg > qg) {
                    v = NEGV;
                } else {
                    int idx = kg - qg;
                    if (idx < -128) idx = -128;
                    v = s4[i][j] * scale + relS[idx + 128];
                }
                Ps[(ty * 4 + i) * PAD + tx * 4 + j] = v;
            }
        }
        __syncthreads();

        if (tid < 64) {
            int r = tid;
            float mold = rowm[r];
            float mx = mold;
            #pragma unroll 8
            for (int c = 0; c < 64; c++) mx = fmaxf(mx, Ps[r * PAD + c]);
            float sum = 0.f;
            #pragma unroll 8
            for (int c = 0; c < 64; c++) {
                float e = __expf(Ps[r * PAD + c] - mx);
                Ps[r * PAD + c] = e;
                sum += e;
            }
            float sc = __expf(mold - mx);
            rowsc[r] = sc;
            rowl[r]  = rowl[r] * sc + sum;
            rowm[r]  = mx;
        }
        __syncthreads();

        #pragma unroll
        for (int i = 0; i < 4; i++) {
            float sc = rowsc[ty * 4 + i];
            #pragma unroll
            for (int j = 0; j < 4; j++) acc[i][j] *= sc;
        }
        #pragma unroll
        for (int kk = 0; kk < 64; kk++) {
            float p[4], v4[4];
            #pragma unroll
            for (int i = 0; i < 4; i++) p[i] = Ps[(ty * 4 + i) * PAD + kk];
            #pragma unroll
            for (int j = 0; j < 4; j++) v4[j] = Vs[kk * PAD + tx * 4 + j];
            #pragma unroll
            for (int i = 0; i < 4; i++)
                #pragma unroll
                for (int j = 0; j < 4; j++)
                    acc[i][j] += p[i] * v4[j];
        }
        __syncthreads();
    }

    #pragma unroll
    for (int i = 0; i < 4; i++) {
        int r = ty * 4 + i;
        float inv = 1.f / rowl[r];
        int qg = qt * QT + r;
        #pragma unroll
        for (int j = 0; j < 4; j++) {
            o[((size_t)b * S_ + qg) * HDIM_ + h * HD_ + tx * 4 + j] = acc[i][j] * inv;
        }
    }
}

#define ATTN_SMEM_BYTES ((4 * QT * PAD + LREL_ + 3 * 64) * (int)sizeof(float))

// ---------------- host orchestration ----------------
extern "C" void kernel_launch(void* const* d_in, const int* in_sizes, int n_in,
                              void* d_out, int out_size) {
    const float* x        = (const float*)d_in[0];
    const float* pe_ln1_g = (const float*)d_in[1];
    const float* pe_ln1_b = (const float*)d_in[2];
    const float* pe_w     = (const float*)d_in[3];
    const float* pe_b     = (const float*)d_in[4];
    const float* pe_ln2_g = (const float*)d_in[5];
    const float* pe_ln2_b = (const float*)d_in[6];
    const float* lnA_g    = (const float*)d_in[7];
    const float* lnA_b    = (const float*)d_in[8];
    const float* qkv_w    = (const float*)d_in[9];
    const float* qkv_b    = (const float*)d_in[10];
    const float* out_w    = (const float*)d_in[11];
    const float* out_b    = (const float*)d_in[12];
    const float* lnF_g    = (const float*)d_in[13];
    const float* lnF_b    = (const float*)d_in[14];
    const float* fc1_w    = (const float*)d_in[15];
    const float* fc1_b    = (const float*)d_in[16];
    const float* fc2_w    = (const float*)d_in[17];
    const float* fc2_b    = (const float*)d_in[18];
    const float* rel_tab  = (const float*)d_in[19];
    const float* final_g  = (const float*)d_in[20];
    const float* final_b  = (const float*)d_in[21];
    const float* head_w   = (const float*)d_in[22];
    const float* head_b   = (const float*)d_in[23];
    float* out = (float*)d_out;

    float *zin, *z, *h, *qkv, *o, *f;
    cudaGetSymbolAddress((void**)&zin, g_zin);
    cudaGetSymbolAddress((void**)&z,   g_z);
    cudaGetSymbolAddress((void**)&h,   g_h);
    cudaGetSymbolAddress((void**)&qkv, g_qkv);
    cudaGetSymbolAddress((void**)&o,   g_o);
    cudaGetSymbolAddress((void**)&f,   g_f);

    cudaFuncSetAttribute(attn_kernel,
                         cudaFuncAttributeMaxDynamicSharedMemorySize,
                         ATTN_SMEM_BYTES);

    // patch embed: LN(1280) -> GEMM -> LN(1024)
    ln_kernel<<<ROWS_, 256>>>(x, pe_ln1_g, pe_ln1_b, zin, INDIM_, 1e-6f);
    gemm_tf32<0><<<dim3(HDIM_ / BN, ROWS_ / BM), 256>>>(zin, pe_w, pe_b, nullptr, h,
                                                        ROWS_, HDIM_, INDIM_);
    ln_kernel<<<ROWS_, 256>>>(h, pe_ln2_g, pe_ln2_b, z, HDIM_, 1e-6f);

    for (int l = 0; l < NL_; l++) {
        const float* qw = qkv_w + (size_t)l * 3 * HDIM_ * HDIM_;
        const float* qb = qkv_b + (size_t)l * 3 * HDIM_;
        const float* ow = out_w + (size_t)l * HDIM_ * HDIM_;
        const float* ob = out_b + (size_t)l * HDIM_;
        const float* f1w = fc1_w + (size_t)l * FF_ * HDIM_;
        const float* f1b = fc1_b + (size_t)l * FF_;
        const float* f2w = fc2_w + (size_t)l * HDIM_ * FF_;
        const float* f2b = fc2_b + (size_t)l * HDIM_;

        ln_kernel<<<ROWS_, 256>>>(z, lnA_g + l * HDIM_, lnA_b + l * HDIM_, h, HDIM_, 1e-5f);
        gemm_tf32<0><<<dim3(3 * HDIM_ / BN, ROWS_ / BM), 256>>>(h, qw, qb, nullptr, qkv,
                                                                ROWS_, 3 * HDIM_, HDIM_);
        attn_kernel<<<dim3(S_ / QT, B_ * NH_), 256, ATTN_SMEM_BYTES>>>(qkv, rel_tab, o);
        gemm_tf32<2><<<dim3(HDIM_ / BN, ROWS_ / BM), 256>>>(o, ow, ob, z, z,
                                                            ROWS_, HDIM_, HDIM_);
        ln_kernel<<<ROWS_, 256>>>(z, lnF_g + l * HDIM_, lnF_b + l * HDIM_, h, HDIM_, 1e-5f);
        gemm_tf32<1><<<dim3(FF_ / BN, ROWS_ / BM), 256>>>(h, f1w, f1b, nullptr, f,
                                                          ROWS_, FF_, HDIM_);
        gemm_tf32<2><<<dim3(HDIM_ / BN, ROWS_ / BM), 256>>>(f, f2w, f2b, z, z,
                                                            ROWS_, HDIM_, FF_);
    }

    ln_kernel<<<ROWS_, 256>>>(z, final_g, final_b, h, HDIM_, 1e-5f);
    gemm_tf32<0><<<dim3((NCLS_ + BN - 1) / BN, ROWS_ / BM), 256>>>(h, head_w, head_b, nullptr,
                                                                   out, ROWS_, NCLS_, HDIM_);
}

// round 5
// speedup vs baseline: 3.5039x; 1.1461x over previous
#include <cuda_runtime.h>
#include <cuda_bf16.h>
#include <math.h>
#include <stdint.h>

// ---------------- problem constants ----------------
#define B_      2
#define S_      1024
#define ROWS_   (B_ * S_)        // 2048
#define HDIM_   1024
#define NH_     16
#define HD_     64
#define NL_     8
#define FF_     4096
#define INDIM_  1280
#define LREL_   257
#define NCLS_   100

// ---------------- scratch (allocation-free) ----------------
__device__ float g_zin[ROWS_ * INDIM_];
__device__ float g_z  [ROWS_ * HDIM_];
__device__ float g_h  [ROWS_ * HDIM_];
__device__ float g_qkv[ROWS_ * 3 * HDIM_];
__device__ float g_o  [ROWS_ * HDIM_];
__device__ float g_f  [ROWS_ * FF_];

// ---------------- LayerNorm: one block per row ----------------
__global__ void __launch_bounds__(256) ln_kernel(const float* __restrict__ in,
                                                 const float* __restrict__ g,
                                                 const float* __restrict__ b,
                                                 float* __restrict__ out,
                                                 int D, float eps) {
    int row = blockIdx.x;
    const float* p = in + (size_t)row * D;
    float s = 0.f, sq = 0.f;
    for (int i = threadIdx.x; i < D; i += 256) {
        float v = p[i];
        s += v; sq += v * v;
    }
    #pragma unroll
    for (int o = 16; o > 0; o >>= 1) {
        s  += __shfl_xor_sync(0xffffffffu, s,  o);
        sq += __shfl_xor_sync(0xffffffffu, sq, o);
    }
    __shared__ float ss[8], ssq[8];
    __shared__ float sm_mean, sm_rstd;
    int w = threadIdx.x >> 5;
    if ((threadIdx.x & 31) == 0) { ss[w] = s; ssq[w] = sq; }
    __syncthreads();
    if (threadIdx.x == 0) {
        float S = 0.f, SQ = 0.f;
        #pragma unroll
        for (int i = 0; i < 8; i++) { S += ss[i]; SQ += ssq[i]; }
        float mean = S / D;
        float var  = SQ / D - mean * mean;
        sm_mean = mean;
        sm_rstd = rsqrtf(var + eps);
    }
    __syncthreads();
    float mean = sm_mean, rstd = sm_rstd;
    float* q = out + (size_t)row * D;
    for (int i = threadIdx.x; i < D; i += 256)
        q[i] = (p[i] - mean) * rstd * g[i] + b[i];
}

// ---------------- common tf32 helpers ----------------
__device__ __forceinline__ uint32_t f2tf(float f) {
    uint32_t u;
    asm("cvt.rna.tf32.f32 %0, %1;" : "=r"(u) : "f"(f));
    return u;
}

__device__ __forceinline__ void mma_tf32(float* c, const uint32_t* a, const uint32_t* b) {
    asm volatile("mma.sync.aligned.m16n8k8.row.col.f32.tf32.tf32.f32 "
                 "{%0,%1,%2,%3}, {%4,%5,%6,%7}, {%8,%9}, {%0,%1,%2,%3};"
                 : "+f"(c[0]), "+f"(c[1]), "+f"(c[2]), "+f"(c[3])
                 : "r"(a[0]), "r"(a[1]), "r"(a[2]), "r"(a[3]),
                   "r"(b[0]), "r"(b[1]));
}

// ---------------- TF32 tensor-core NT GEMM ----------------
#define BM 128
#define BN 128
#define BK 16
#define SA 136   // smem k-row stride in floats (128 + 8 pad)

// swizzled smem index: row k, logical column c (0..127)
__device__ __forceinline__ int sw(int k, int c) {
    return k * SA + (c ^ (((k >> 2) & 3) << 3));
}

template <int EPI>
__global__ void __launch_bounds__(256, 2) gemm_tf32(const float* __restrict__ A,
                                                    const float* __restrict__ W,
                                                    const float* __restrict__ bias,
                                                    const float* __restrict__ res,
                                                    float* __restrict__ C,
                                                    int M, int N, int K) {
    __shared__ uint32_t As[2][BK * SA];
    __shared__ uint32_t Ws[2][BK * SA];

    const int tid  = threadIdx.x;
    const int lane = tid & 31;
    const int warp = tid >> 5;
    const int wm   = (warp & 1) * 64;
    const int wn   = (warp >> 1) * 32;
    const int m0   = blockIdx.y * BM;
    const int n0   = blockIdx.x * BN;

    float acc[4][4][4] = {};
    float4 ar[2], wr[2];

    {
        #pragma unroll
        for (int i = 0; i < 2; i++) {
            int lin = tid + 256 * i;
            int r = lin >> 2, kq = (lin & 3) * 4;
            float4 va = *(const float4*)&A[(size_t)(m0 + r) * K + kq];
            float4 vw;
            int n = n0 + r;
            if (n < N) vw = *(const float4*)&W[(size_t)n * K + kq];
            else       vw = make_float4(0.f, 0.f, 0.f, 0.f);
            As[0][sw(kq + 0, r)] = f2tf(va.x);
            As[0][sw(kq + 1, r)] = f2tf(va.y);
            As[0][sw(kq + 2, r)] = f2tf(va.z);
            As[0][sw(kq + 3, r)] = f2tf(va.w);
            Ws[0][sw(kq + 0, r)] = f2tf(vw.x);
            Ws[0][sw(kq + 1, r)] = f2tf(vw.y);
            Ws[0][sw(kq + 2, r)] = f2tf(vw.z);
            Ws[0][sw(kq + 3, r)] = f2tf(vw.w);
        }
    }
    __syncthreads();

    const int nchunks = K / BK;
    int buf = 0;
    for (int c = 0; c < nchunks; c++) {
        const bool has_next = (c + 1 < nchunks);
        const int k0n = (c + 1) * BK;
        if (has_next) {
            #pragma unroll
            for (int i = 0; i < 2; i++) {
                int lin = tid + 256 * i;
                int r = lin >> 2, kq = (lin & 3) * 4;
                ar[i] = *(const float4*)&A[(size_t)(m0 + r) * K + k0n + kq];
                int n = n0 + r;
                if (n < N) wr[i] = *(const float4*)&W[(size_t)n * K + k0n + kq];
                else       wr[i] = make_float4(0.f, 0.f, 0.f, 0.f);
            }
        }

        const uint32_t* Ab = As[buf];
        const uint32_t* Wb = Ws[buf];
        #pragma unroll
        for (int ks = 0; ks < BK; ks += 8) {
            const int kq0 = (ks >> 2) & 3;
            const int kq1 = kq0 + 1;
            const int krow0 = ks + (lane & 3);
            const int krow1 = ks + 4 + (lane & 3);
            uint32_t af[4][4];
            #pragma unroll
            for (int mt = 0; mt < 4; mt++) {
                int mb = wm + mt * 16 + (lane >> 2);
                af[mt][0] = Ab[krow0 * SA + ( mb      ^ (kq0 << 3))];
                af[mt][1] = Ab[krow0 * SA + ((mb + 8) ^ (kq0 << 3))];
                af[mt][2] = Ab[krow1 * SA + ( mb      ^ (kq1 << 3))];
                af[mt][3] = Ab[krow1 * SA + ((mb + 8) ^ (kq1 << 3))];
            }
            uint32_t bf[4][2];
            #pragma unroll
            for (int nt = 0; nt < 4; nt++) {
                int nb = wn + nt * 8 + (lane >> 2);
                bf[nt][0] = Wb[krow0 * SA + (nb ^ (kq0 << 3))];
                bf[nt][1] = Wb[krow1 * SA + (nb ^ (kq1 << 3))];
            }
            #pragma unroll
            for (int mt = 0; mt < 4; mt++)
                #pragma unroll
                for (int nt = 0; nt < 4; nt++)
                    mma_tf32(acc[mt][nt], af[mt], bf[nt]);
        }

        if (has_next) {
            int nb = buf ^ 1;
            #pragma unroll
            for (int i = 0; i < 2; i++) {
                int lin = tid + 256 * i;
                int r = lin >> 2, kq = (lin & 3) * 4;
                As[nb][sw(kq + 0, r)] = f2tf(ar[i].x);
                As[nb][sw(kq + 1, r)] = f2tf(ar[i].y);
                As[nb][sw(kq + 2, r)] = f2tf(ar[i].z);
                As[nb][sw(kq + 3, r)] = f2tf(ar[i].w);
                Ws[nb][sw(kq + 0, r)] = f2tf(wr[i].x);
                Ws[nb][sw(kq + 1, r)] = f2tf(wr[i].y);
                Ws[nb][sw(kq + 2, r)] = f2tf(wr[i].z);
                Ws[nb][sw(kq + 3, r)] = f2tf(wr[i].w);
            }
            __syncthreads();
            buf = nb;
        }
    }

    #pragma unroll
    for (int mt = 0; mt < 4; mt++) {
        const int r0 = m0 + wm + mt * 16 + (lane >> 2);
        #pragma unroll
        for (int nt = 0; nt < 4; nt++) {
            const int c0 = n0 + wn + nt * 8 + (lane & 3) * 2;
            const float* a4 = acc[mt][nt];
            #pragma unroll
            for (int e = 0; e < 4; e++) {
                int r = r0 + (e >> 1) * 8;
                int cc = c0 + (e & 1);
                if (cc < N) {
                    float v = a4[e] + bias[cc];
                    if (EPI == 1) {
                        v = 0.5f * v * (1.0f + erff(v * 0.70710678118654752f));
                    } else if (EPI == 2) {
                        v += res[(size_t)r * N + cc];
                    }
                    C[(size_t)r * N + cc] = v;
                }
            }
        }
    }
}

// ---------------- tensor-core causal flash attention (tf32) ----------------
// block = 256 thr / 8 warps; one (b, h, 128-row q tile). K/V tiles of 64.
#define AQT 128
#define AKT 64
#define AST 68   // smem row stride (floats)

__global__ void __launch_bounds__(256) attn_mma(const float* __restrict__ qkv,
                                                const float* __restrict__ rel,
                                                float* __restrict__ o) {
    extern __shared__ uint32_t smu[];
    uint32_t* Qs = smu;                     // 128 x 68
    uint32_t* Ks = Qs + AQT * AST;          // 64 x 68
    uint32_t* Vs = Ks + AKT * AST;          // 64 x 68
    uint32_t* Ps = Vs + AKT * AST;          // 128 x 68
    float*  relS = (float*)(Ps + AQT * AST);  // 257

    const int tid  = threadIdx.x;
    const int lane = tid & 31;
    const int warp = tid >> 5;
    const int qt   = (int)(gridDim.x - 1) - (int)blockIdx.x;  // heavy tiles first
    const int b    = blockIdx.y >> 4;
    const int h    = blockIdx.y & 15;

    const size_t base = (size_t)b * S_ * 3 * HDIM_ + (size_t)h * HD_;

    for (int i = tid; i < LREL_; i += 256) relS[i] = rel[h * LREL_ + i];

    // load Q tile (scaled by 1/sqrt(64) = 0.125, exact in tf32)
    for (int i = tid; i < AQT * 16; i += 256) {
        int r = i >> 4, c4 = (i & 15) * 4;
        float4 v = *(const float4*)&qkv[base + (size_t)(qt * AQT + r) * (3 * HDIM_) + c4];
        Qs[r * AST + c4 + 0] = f2tf(v.x * 0.125f);
        Qs[r * AST + c4 + 1] = f2tf(v.y * 0.125f);
        Qs[r * AST + c4 + 2] = f2tf(v.z * 0.125f);
        Qs[r * AST + c4 + 3] = f2tf(v.w * 0.125f);
    }

    const int rbase = warp * 16;
    const int rsub  = lane >> 2;            // 0..7
    const int cq    = lane & 3;             // 0..3
    const int r0    = rbase + rsub;

    float m0 = -INFINITY, m1 = -INFINITY, l0 = 0.f, l1 = 0.f;
    float acc[8][4] = {};

    const int nkt = 2 * qt + 2;
    for (int kt = 0; kt < nkt; kt++) {
        __syncthreads();
        // load K/V tiles 64x64
        for (int i = tid; i < AKT * 16; i += 256) {
            int r = i >> 4, c4 = (i & 15) * 4;
            size_t g = base + (size_t)(kt * AKT + r) * (3 * HDIM_) + c4;
            float4 kv = *(const float4*)&qkv[g + HDIM_];
            float4 vv = *(const float4*)&qkv[g + 2 * HDIM_];
            Ks[r * AST + c4 + 0] = f2tf(kv.x);
            Ks[r * AST + c4 + 1] = f2tf(kv.y);
            Ks[r * AST + c4 + 2] = f2tf(kv.z);
            Ks[r * AST + c4 + 3] = f2tf(kv.w);
            Vs[r * AST + c4 + 0] = f2tf(vv.x);
            Vs[r * AST + c4 + 1] = f2tf(vv.y);
            Vs[r * AST + c4 + 2] = f2tf(vv.z);
            Vs[r * AST + c4 + 3] = f2tf(vv.w);
        }
        __syncthreads();

        // ---- S = Q K^T : warp computes 16 x 64 ----
        float sc[8][4] = {};
        #pragma unroll
        for (int ks = 0; ks < AKT; ks += 8) {
            uint32_t a[4];
            a[0] = Qs[(r0    ) * AST + ks + cq    ];
            a[1] = Qs[(r0 + 8) * AST + ks + cq    ];
            a[2] = Qs[(r0    ) * AST + ks + cq + 4];
            a[3] = Qs[(r0 + 8) * AST + ks + cq + 4];
            #pragma unroll
            for (int j = 0; j < 8; j++) {
                uint32_t bfr[2];
                bfr[0] = Ks[(j * 8 + rsub) * AST + ks + cq    ];
                bfr[1] = Ks[(j * 8 + rsub) * AST + ks + cq + 4];
                mma_tf32(sc[j], a, bfr);
            }
        }

        // ---- bias + causal mask + online softmax ----
        const int q0g = qt * AQT + r0;
        const int q1g = q0g + 8;
        const int kc0 = kt * AKT + cq * 2;
        float rmax0 = -INFINITY, rmax1 = -INFINITY;
        #pragma unroll
        for (int j = 0; j < 8; j++) {
            int ka = kc0 + j * 8, kb = ka + 1;
            sc[j][0] = (ka > q0g) ? -INFINITY : sc[j][0] + relS[max(ka - q0g, -128) + 128];
            sc[j][1] = (kb > q0g) ? -INFINITY : sc[j][1] + relS[max(kb - q0g, -128) + 128];
            sc[j][2] = (ka > q1g) ? -INFINITY : sc[j][2] + relS[max(ka - q1g, -128) + 128];
            sc[j][3] = (kb > q1g) ? -INFINITY : sc[j][3] + relS[max(kb - q1g, -128) + 128];
            rmax0 = fmaxf(rmax0, fmaxf(sc[j][0], sc[j][1]));
            rmax1 = fmaxf(rmax1, fmaxf(sc[j][2], sc[j][3]));
        }
        rmax0 = fmaxf(rmax0, __shfl_xor_sync(0xffffffffu, rmax0, 1));
        rmax0 = fmaxf(rmax0, __shfl_xor_sync(0xffffffffu, rmax0, 2));
        rmax1 = fmaxf(rmax1, __shfl_xor_sync(0xffffffffu, rmax1, 1));
        rmax1 = fmaxf(rmax1, __shfl_xor_sync(0xffffffffu, rmax1, 2));

        float mx0 = fmaxf(m0, rmax0);
        float mx1 = fmaxf(m1, rmax1);
        float sum0 = 0.f, sum1 = 0.f;
        #pragma unroll
        for (int j = 0; j < 8; j++) {
            sc[j][0] = __expf(sc[j][0] - mx0);
            sc[j][1] = __expf(sc[j][1] - mx0);
            sc[j][2] = __expf(sc[j][2] - mx1);
            sc[j][3] = __expf(sc[j][3] - mx1);
            sum0 += sc[j][0] + sc[j][1];
            sum1 += sc[j][2] + sc[j][3];
        }
        sum0 += __shfl_xor_sync(0xffffffffu, sum0, 1);
        sum0 += __shfl_xor_sync(0xffffffffu, sum0, 2);
        sum1 += __shfl_xor_sync(0xffffffffu, sum1, 1);
        sum1 += __shfl_xor_sync(0xffffffffu, sum1, 2);

        float f0 = __expf(m0 - mx0);
        float f1 = __expf(m1 - mx1);
        l0 = l0 * f0 + sum0;
        l1 = l1 * f1 + sum1;
        m0 = mx0; m1 = mx1;

        #pragma unroll
        for (int j = 0; j < 8; j++) {
            acc[j][0] *= f0; acc[j][1] *= f0;
            acc[j][2] *= f1; acc[j][3] *= f1;
        }

        // store P (tf32) to this warp's private smem stripe
        #pragma unroll
        for (int j = 0; j < 8; j++) {
            int c = j * 8 + cq * 2;
            Ps[(r0    ) * AST + c    ] = f2tf(sc[j][0]);
            Ps[(r0    ) * AST + c + 1] = f2tf(sc[j][1]);
            Ps[(r0 + 8) * AST + c    ] = f2tf(sc[j][2]);
            Ps[(r0 + 8) * AST + c + 1] = f2tf(sc[j][3]);
        }
        __syncwarp();

        // ---- O += P V : 16 x 64 (d) x 64 (kv) ----
        #pragma unroll
        for (int ks = 0; ks < AKT; ks += 8) {
            uint32_t a[4];
            a[0] = Ps[(r0    ) * AST + ks + cq    ];
            a[1] = Ps[(r0 + 8) * AST + ks + cq    ];
            a[2] = Ps[(r0    ) * AST + ks + cq + 4];
            a[3] = Ps[(r0 + 8) * AST + ks + cq + 4];
            #pragma unroll
            for (int j = 0; j < 8; j++) {
                uint32_t bfr[2];
                bfr[0] = Vs[(ks + cq    ) * AST + j * 8 + rsub];
                bfr[1] = Vs[(ks + cq + 4) * AST + j * 8 + rsub];
                mma_tf32(acc[j], a, bfr);
            }
        }
        __syncwarp();
    }

    // ---- write O ----
    const float inv0 = 1.f / l0;
    const float inv1 = 1.f / l1;
    const int q0g = qt * AQT + r0;
    #pragma unroll
    for (int j = 0; j < 8; j++) {
        int col = h * HD_ + j * 8 + cq * 2;
        float2 v0 = make_float2(acc[j][0] * inv0, acc[j][1] * inv0);
        float2 v1 = make_float2(acc[j][2] * inv1, acc[j][3] * inv1);
        *(float2*)&o[((size_t)b * S_ + q0g    ) * HDIM_ + col] = v0;
        *(float2*)&o[((size_t)b * S_ + q0g + 8) * HDIM_ + col] = v1;
    }
}

#define ATTN_SMEM_BYTES (((AQT + AKT + AKT + AQT) * AST + LREL_) * (int)sizeof(float))

// ---------------- host orchestration ----------------
extern "C" void kernel_launch(void* const* d_in, const int* in_sizes, int n_in,
                              void* d_out, int out_size) {
    const float* x        = (const float*)d_in[0];
    const float* pe_ln1_g = (const float*)d_in[1];
    const float* pe_ln1_b = (const float*)d_in[2];
    const float* pe_w     = (const float*)d_in[3];
    const float* pe_b     = (const float*)d_in[4];
    const float* pe_ln2_g = (const float*)d_in[5];
    const float* pe_ln2_b = (const float*)d_in[6];
    const float* lnA_g    = (const float*)d_in[7];
    const float* lnA_b    = (const float*)d_in[8];
    const float* qkv_w    = (const float*)d_in[9];
    const float* qkv_b    = (const float*)d_in[10];
    const float* out_w    = (const float*)d_in[11];
    const float* out_b    = (const float*)d_in[12];
    const float* lnF_g    = (const float*)d_in[13];
    const float* lnF_b    = (const float*)d_in[14];
    const float* fc1_w    = (const float*)d_in[15];
    const float* fc1_b    = (const float*)d_in[16];
    const float* fc2_w    = (const float*)d_in[17];
    const float* fc2_b    = (const float*)d_in[18];
    const float* rel_tab  = (const float*)d_in[19];
    const float* final_g  = (const float*)d_in[20];
    const float* final_b  = (const float*)d_in[21];
    const float* head_w   = (const float*)d_in[22];
    const float* head_b   = (const float*)d_in[23];
    float* out = (float*)d_out;

    float *zin, *z, *h, *qkv, *o, *f;
    cudaGetSymbolAddress((void**)&zin, g_zin);
    cudaGetSymbolAddress((void**)&z,   g_z);
    cudaGetSymbolAddress((void**)&h,   g_h);
    cudaGetSymbolAddress((void**)&qkv, g_qkv);
    cudaGetSymbolAddress((void**)&o,   g_o);
    cudaGetSymbolAddress((void**)&f,   g_f);

    cudaFuncSetAttribute(attn_mma,
                         cudaFuncAttributeMaxDynamicSharedMemorySize,
                         ATTN_SMEM_BYTES);

    // patch embed: LN(1280) -> GEMM -> LN(1024)
    ln_kernel<<<ROWS_, 256>>>(x, pe_ln1_g, pe_ln1_b, zin, INDIM_, 1e-6f);
    gemm_tf32<0><<<dim3(HDIM_ / BN, ROWS_ / BM), 256>>>(zin, pe_w, pe_b, nullptr, h,
                                                        ROWS_, HDIM_, INDIM_);
    ln_kernel<<<ROWS_, 256>>>(h, pe_ln2_g, pe_ln2_b, z, HDIM_, 1e-6f);

    for (int l = 0; l < NL_; l++) {
        const float* qw = qkv_w + (size_t)l * 3 * HDIM_ * HDIM_;
        const float* qb = qkv_b + (size_t)l * 3 * HDIM_;
        const float* ow = out_w + (size_t)l * HDIM_ * HDIM_;
        const float* ob = out_b + (size_t)l * HDIM_;
        const float* f1w = fc1_w + (size_t)l * FF_ * HDIM_;
        const float* f1b = fc1_b + (size_t)l * FF_;
        const float* f2w = fc2_w + (size_t)l * HDIM_ * FF_;
        const float* f2b = fc2_b + (size_t)l * HDIM_;

        ln_kernel<<<ROWS_, 256>>>(z, lnA_g + l * HDIM_, lnA_b + l * HDIM_, h, HDIM_, 1e-5f);
        gemm_tf32<0><<<dim3(3 * HDIM_ / BN, ROWS_ / BM), 256>>>(h, qw, qb, nullptr, qkv,
                                                                ROWS_, 3 * HDIM_, HDIM_);
        attn_mma<<<dim3(S_ / AQT, B_ * NH_), 256, ATTN_SMEM_BYTES>>>(qkv, rel_tab, o);
        gemm_tf32<2><<<dim3(HDIM_ / BN, ROWS_ / BM), 256>>>(o, ow, ob, z, z,
                                                            ROWS_, HDIM_, HDIM_);
        ln_kernel<<<ROWS_, 256>>>(z, lnF_g + l * HDIM_, lnF_b + l * HDIM_, h, HDIM_, 1e-5f);
        gemm_tf32<1><<<dim3(FF_ / BN, ROWS_ / BM), 256>>>(h, f1w, f1b, nullptr, f,
                                                          ROWS_, FF_, HDIM_);
        gemm_tf32<2><<<dim3(HDIM_ / BN, ROWS_ / BM), 256>>>(f, f2w, f2b, z, z,
                                                            ROWS_, HDIM_, FF_);
    }

    ln_kernel<<<ROWS_, 256>>>(z, final_g, final_b, h, HDIM_, 1e-5f);
    gemm_tf32<0><<<dim3((NCLS_ + BN - 1) / BN, ROWS_ / BM), 256>>>(h, head_w, head_b, nullptr,
                                                                   out, ROWS_, NCLS_, HDIM_);
}

// round 10
// speedup vs baseline: 4.1971x; 1.1978x over previous
#include <cuda_runtime.h>
#include <cuda_bf16.h>
#include <math.h>
#include <stdint.h>

// ---------------- problem constants ----------------
#define B_      2
#define S_      1024
#define ROWS_   (B_ * S_)        // 2048
#define HDIM_   1024
#define NH_     16
#define HD_     64
#define NL_     8
#define FF_     4096
#define INDIM_  1280
#define LREL_   257
#define NCLS_   100

// ---------------- scratch (allocation-free) ----------------
__device__ float g_zin[ROWS_ * INDIM_];
__device__ float g_z  [ROWS_ * HDIM_];
__device__ float g_h  [ROWS_ * HDIM_];
__device__ float g_qkv[ROWS_ * 3 * HDIM_];
__device__ float g_o  [ROWS_ * HDIM_];
__device__ float g_f  [ROWS_ * FF_];

// ---------------- LayerNorm: one block per row ----------------
__global__ void __launch_bounds__(256) ln_kernel(const float* __restrict__ in,
                                                 const float* __restrict__ g,
                                                 const float* __restrict__ b,
                                                 float* __restrict__ out,
                                                 int D, float eps) {
    int row = blockIdx.x;
    const float* p = in + (size_t)row * D;
    float s = 0.f, sq = 0.f;
    for (int i = threadIdx.x; i < D; i += 256) {
        float v = p[i];
        s += v; sq += v * v;
    }
    #pragma unroll
    for (int o = 16; o > 0; o >>= 1) {
        s  += __shfl_xor_sync(0xffffffffu, s,  o);
        sq += __shfl_xor_sync(0xffffffffu, sq, o);
    }
    __shared__ float ss[8], ssq[8];
    __shared__ float sm_mean, sm_rstd;
    int w = threadIdx.x >> 5;
    if ((threadIdx.x & 31) == 0) { ss[w] = s; ssq[w] = sq; }
    __syncthreads();
    if (threadIdx.x == 0) {
        float S = 0.f, SQ = 0.f;
        #pragma unroll
        for (int i = 0; i < 8; i++) { S += ss[i]; SQ += ssq[i]; }
        float mean = S / D;
        float var  = SQ / D - mean * mean;
        sm_mean = mean;
        sm_rstd = rsqrtf(var + eps);
    }
    __syncthreads();
    float mean = sm_mean, rstd = sm_rstd;
    float* q = out + (size_t)row * D;
    for (int i = threadIdx.x; i < D; i += 256)
        q[i] = (p[i] - mean) * rstd * g[i] + b[i];
}

// ---------------- common tf32 helpers ----------------
__device__ __forceinline__ uint32_t f2tf(float f) {
    uint32_t u;
    asm("cvt.rna.tf32.f32 %0, %1;" : "=r"(u) : "f"(f));
    return u;
}

__device__ __forceinline__ void mma_tf32(float* c, const uint32_t* a, const uint32_t* b) {
    asm volatile("mma.sync.aligned.m16n8k8.row.col.f32.tf32.tf32.f32 "
                 "{%0,%1,%2,%3}, {%4,%5,%6,%7}, {%8,%9}, {%0,%1,%2,%3};"
                 : "+f"(c[0]), "+f"(c[1]), "+f"(c[2]), "+f"(c[3])
                 : "r"(a[0]), "r"(a[1]), "r"(a[2]), "r"(a[3]),
                   "r"(b[0]), "r"(b[1]));
}

// ---------------- TF32 tensor-core NT GEMM ----------------
#define BM 128
#define BN 128
#define BK 32
#define SA 136   // smem k-row stride in floats (128 + 8 pad)
#define GEMM_SMEM_BYTES (4 * BK * SA * (int)sizeof(uint32_t))  // 2 bufs x (A + W)

// swizzled smem index: row k, logical column c (0..127)
__device__ __forceinline__ int sw(int k, int c) {
    return k * SA + (c ^ (((k >> 2) & 3) << 3));
}

template <int EPI>
__global__ void __launch_bounds__(256, 1) gemm_tf32(const float* __restrict__ A,
                                                    const float* __restrict__ W,
                                                    const float* __restrict__ bias,
                                                    const float* __restrict__ res,
                                                    float* __restrict__ C,
                                                    int M, int N, int K) {
    extern __shared__ uint32_t dynsm[];
    uint32_t* As = dynsm;                    // [2][BK*SA]
    uint32_t* Ws = dynsm + 2 * BK * SA;      // [2][BK*SA]

    const int tid  = threadIdx.x;
    const int lane = tid & 31;
    const int warp = tid >> 5;
    const int wm   = (warp & 1) * 64;
    const int wn   = (warp >> 1) * 32;
    const int m0   = blockIdx.y * BM;
    const int n0   = blockIdx.x * BN;

    float acc[4][4][4] = {};
    float4 ar[4], wr[4];

    // ---- load chunk 0 into buf 0 ----
    #pragma unroll
    for (int i = 0; i < 4; i++) {
        int lin = tid + 256 * i;
        int r = lin >> 3, kq = (lin & 7) * 4;
        float4 va = *(const float4*)&A[(size_t)(m0 + r) * K + kq];
        float4 vw;
        int n = n0 + r;
        if (n < N) vw = *(const float4*)&W[(size_t)n * K + kq];
        else       vw = make_float4(0.f, 0.f, 0.f, 0.f);
        As[sw(kq + 0, r)] = f2tf(va.x);
        As[sw(kq + 1, r)] = f2tf(va.y);
        As[sw(kq + 2, r)] = f2tf(va.z);
        As[sw(kq + 3, r)] = f2tf(va.w);
        Ws[sw(kq + 0, r)] = f2tf(vw.x);
        Ws[sw(kq + 1, r)] = f2tf(vw.y);
        Ws[sw(kq + 2, r)] = f2tf(vw.z);
        Ws[sw(kq + 3, r)] = f2tf(vw.w);
    }
    __syncthreads();

    const int nchunks = K / BK;
    int buf = 0;
    for (int c = 0; c < nchunks; c++) {
        const bool has_next = (c + 1 < nchunks);
        const int k0n = (c + 1) * BK;
        if (has_next) {
            #pragma unroll
            for (int i = 0; i < 4; i++) {
                int lin = tid + 256 * i;
                int r = lin >> 3, kq = (lin & 7) * 4;
                ar[i] = *(const float4*)&A[(size_t)(m0 + r) * K + k0n + kq];
                int n = n0 + r;
                if (n < N) wr[i] = *(const float4*)&W[(size_t)n * K + k0n + kq];
                else       wr[i] = make_float4(0.f, 0.f, 0.f, 0.f);
            }
        }

        const uint32_t* Ab = As + buf * (BK * SA);
        const uint32_t* Wb = Ws + buf * (BK * SA);
        #pragma unroll
        for (int ks = 0; ks < BK; ks += 8) {
            const int kq0 = (ks >> 2) & 3;
            const int kq1 = kq0 + 1;
            const int krow0 = ks + (lane & 3);
            const int krow1 = ks + 4 + (lane & 3);
            uint32_t af[4][4];
            #pragma unroll
            for (int mt = 0; mt < 4; mt++) {
                int mb = wm + mt * 16 + (lane >> 2);
                af[mt][0] = Ab[krow0 * SA + ( mb      ^ (kq0 << 3))];
                af[mt][1] = Ab[krow0 * SA + ((mb + 8) ^ (kq0 << 3))];
                af[mt][2] = Ab[krow1 * SA + ( mb      ^ (kq1 << 3))];
                af[mt][3] = Ab[krow1 * SA + ((mb + 8) ^ (kq1 << 3))];
            }
            uint32_t bf[4][2];
            #pragma unroll
            for (int nt = 0; nt < 4; nt++) {
                int nb = wn + nt * 8 + (lane >> 2);
                bf[nt][0] = Wb[krow0 * SA + (nb ^ (kq0 << 3))];
                bf[nt][1] = Wb[krow1 * SA + (nb ^ (kq1 << 3))];
            }
            #pragma unroll
            for (int mt = 0; mt < 4; mt++)
                #pragma unroll
                for (int nt = 0; nt < 4; nt++)
                    mma_tf32(acc[mt][nt], af[mt], bf[nt]);
        }

        if (has_next) {
            int nb = buf ^ 1;
            uint32_t* An = As + nb * (BK * SA);
            uint32_t* Wn = Ws + nb * (BK * SA);
            #pragma unroll
            for (int i = 0; i < 4; i++) {
                int lin = tid + 256 * i;
                int r = lin >> 3, kq = (lin & 7) * 4;
                An[sw(kq + 0, r)] = f2tf(ar[i].x);
                An[sw(kq + 1, r)] = f2tf(ar[i].y);
                An[sw(kq + 2, r)] = f2tf(ar[i].z);
                An[sw(kq + 3, r)] = f2tf(ar[i].w);
                Wn[sw(kq + 0, r)] = f2tf(wr[i].x);
                Wn[sw(kq + 1, r)] = f2tf(wr[i].y);
                Wn[sw(kq + 2, r)] = f2tf(wr[i].z);
                Wn[sw(kq + 3, r)] = f2tf(wr[i].w);
            }
            __syncthreads();
            buf = nb;
        }
    }

    // ---- epilogue ----
    #pragma unroll
    for (int mt = 0; mt < 4; mt++) {
        const int r0 = m0 + wm + mt * 16 + (lane >> 2);
        #pragma unroll
        for (int nt = 0; nt < 4; nt++) {
            const int c0 = n0 + wn + nt * 8 + (lane & 3) * 2;
            const float* a4 = acc[mt][nt];
            #pragma unroll
            for (int e = 0; e < 4; e++) {
                int r = r0 + (e >> 1) * 8;
                int cc = c0 + (e & 1);
                if (cc < N) {
                    float v = a4[e] + bias[cc];
                    if (EPI == 1) {
                        v = 0.5f * v * (1.0f + erff(v * 0.70710678118654752f));
                    } else if (EPI == 2) {
                        v += res[(size_t)r * N + cc];
                    }
                    C[(size_t)r * N + cc] = v;
                }
            }
        }
    }
}

// ---------------- tensor-core causal flash attention (tf32) ----------------
#define AQT 128
#define AKT 64
#define AST 68   // smem row stride (floats)

__global__ void __launch_bounds__(256) attn_mma(const float* __restrict__ qkv,
                                                const float* __restrict__ rel,
                                                float* __restrict__ o) {
    extern __shared__ uint32_t smu[];
    uint32_t* Qs = smu;                     // 128 x 68
    uint32_t* Ks = Qs + AQT * AST;          // 64 x 68
    uint32_t* Vs = Ks + AKT * AST;          // 64 x 68
    uint32_t* Ps = Vs + AKT * AST;          // 128 x 68
    float*  relS = (float*)(Ps + AQT * AST);  // 257

    const int tid  = threadIdx.x;
    const int lane = tid & 31;
    const int warp = tid >> 5;
    const int qt   = (int)(gridDim.x - 1) - (int)blockIdx.x;  // heavy tiles first
    const int b    = blockIdx.y >> 4;
    const int h    = blockIdx.y & 15;

    const size_t base = (size_t)b * S_ * 3 * HDIM_ + (size_t)h * HD_;

    for (int i = tid; i < LREL_; i += 256) relS[i] = rel[h * LREL_ + i];

    // load Q tile (scaled by 1/sqrt(64) = 0.125, exact in tf32)
    for (int i = tid; i < AQT * 16; i += 256) {
        int r = i >> 4, c4 = (i & 15) * 4;
        float4 v = *(const float4*)&qkv[base + (size_t)(qt * AQT + r) * (3 * HDIM_) + c4];
        Qs[r * AST + c4 + 0] = f2tf(v.x * 0.125f);
        Qs[r * AST + c4 + 1] = f2tf(v.y * 0.125f);
        Qs[r * AST + c4 + 2] = f2tf(v.z * 0.125f);
        Qs[r * AST + c4 + 3] = f2tf(v.w * 0.125f);
    }

    const int rbase = warp * 16;
    const int rsub  = lane >> 2;            // 0..7
    const int cq    = lane & 3;             // 0..3
    const int r0    = rbase + rsub;

    float m0 = -INFINITY, m1 = -INFINITY, l0 = 0.f, l1 = 0.f;
    float acc[8][4] = {};

    const int nkt = 2 * qt + 2;
    for (int kt = 0; kt < nkt; kt++) {
        __syncthreads();
        for (int i = tid; i < AKT * 16; i += 256) {
            int r = i >> 4, c4 = (i & 15) * 4;
            size_t g = base + (size_t)(kt * AKT + r) * (3 * HDIM_) + c4;
            float4 kv = *(const float4*)&qkv[g + HDIM_];
            float4 vv = *(const float4*)&qkv[g + 2 * HDIM_];
            Ks[r * AST + c4 + 0] = f2tf(kv.x);
            Ks[r * AST + c4 + 1] = f2tf(kv.y);
            Ks[r * AST + c4 + 2] = f2tf(kv.z);
            Ks[r * AST + c4 + 3] = f2tf(kv.w);
            Vs[r * AST + c4 + 0] = f2tf(vv.x);
            Vs[r * AST + c4 + 1] = f2tf(vv.y);
            Vs[r * AST + c4 + 2] = f2tf(vv.z);
            Vs[r * AST + c4 + 3] = f2tf(vv.w);
        }
        __syncthreads();

        // ---- S = Q K^T : warp computes 16 x 64 ----
        float sc[8][4] = {};
        #pragma unroll
        for (int ks = 0; ks < AKT; ks += 8) {
            uint32_t a[4];
            a[0] = Qs[(r0    ) * AST + ks + cq    ];
            a[1] = Qs[(r0 + 8) * AST + ks + cq    ];
            a[2] = Qs[(r0    ) * AST + ks + cq + 4];
            a[3] = Qs[(r0 + 8) * AST + ks + cq + 4];
            #pragma unroll
            for (int j = 0; j < 8; j++) {
                uint32_t bfr[2];
                bfr[0] = Ks[(j * 8 + rsub) * AST + ks + cq    ];
                bfr[1] = Ks[(j * 8 + rsub) * AST + ks + cq + 4];
                mma_tf32(sc[j], a, bfr);
            }
        }

        // ---- bias + causal mask + online softmax ----
        const int q0g = qt * AQT + r0;
        const int q1g = q0g + 8;
        const int kc0 = kt * AKT + cq * 2;
        float rmax0 = -INFINITY, rmax1 = -INFINITY;
        #pragma unroll
        for (int j = 0; j < 8; j++) {
            int ka = kc0 + j * 8, kb = ka + 1;
            sc[j][0] = (ka > q0g) ? -INFINITY : sc[j][0] + relS[max(ka - q0g, -128) + 128];
            sc[j][1] = (kb > q0g) ? -INFINITY : sc[j][1] + relS[max(kb - q0g, -128) + 128];
            sc[j][2] = (ka > q1g) ? -INFINITY : sc[j][2] + relS[max(ka - q1g, -128) + 128];
            sc[j][3] = (kb > q1g) ? -INFINITY : sc[j][3] + relS[max(kb - q1g, -128) + 128];
            rmax0 = fmaxf(rmax0, fmaxf(sc[j][0], sc[j][1]));
            rmax1 = fmaxf(rmax1, fmaxf(sc[j][2], sc[j][3]));
        }
        rmax0 = fmaxf(rmax0, __shfl_xor_sync(0xffffffffu, rmax0, 1));
        rmax0 = fmaxf(rmax0, __shfl_xor_sync(0xffffffffu, rmax0, 2));
        rmax1 = fmaxf(rmax1, __shfl_xor_sync(0xffffffffu, rmax1, 1));
        rmax1 = fmaxf(rmax1, __shfl_xor_sync(0xffffffffu, rmax1, 2));

        float mx0 = fmaxf(m0, rmax0);
        float mx1 = fmaxf(m1, rmax1);
        float sum0 = 0.f, sum1 = 0.f;
        #pragma unroll
        for (int j = 0; j < 8; j++) {
            sc[j][0] = __expf(sc[j][0] - mx0);
            sc[j][1] = __expf(sc[j][1] - mx0);
            sc[j][2] = __expf(sc[j][2] - mx1);
            sc[j][3] = __expf(sc[j][3] - mx1);
            sum0 += sc[j][0] + sc[j][1];
            sum1 += sc[j][2] + sc[j][3];
        }
        sum0 += __shfl_xor_sync(0xffffffffu, sum0, 1);
        sum0 += __shfl_xor_sync(0xffffffffu, sum0, 2);
        sum1 += __shfl_xor_sync(0xffffffffu, sum1, 1);
        sum1 += __shfl_xor_sync(0xffffffffu, sum1, 2);

        float f0 = __expf(m0 - mx0);
        float f1 = __expf(m1 - mx1);
        l0 = l0 * f0 + sum0;
        l1 = l1 * f1 + sum1;
        m0 = mx0; m1 = mx1;

        #pragma unroll
        for (int j = 0; j < 8; j++) {
            acc[j][0] *= f0; acc[j][1] *= f0;
            acc[j][2] *= f1; acc[j][3] *= f1;
        }

        #pragma unroll
        for (int j = 0; j < 8; j++) {
            int c = j * 8 + cq * 2;
            Ps[(r0    ) * AST + c    ] = f2tf(sc[j][0]);
            Ps[(r0    ) * AST + c + 1] = f2tf(sc[j][1]);
            Ps[(r0 + 8) * AST + c    ] = f2tf(sc[j][2]);
            Ps[(r0 + 8) * AST + c + 1] = f2tf(sc[j][3]);
        }
        __syncwarp();

        // ---- O += P V ----
        #pragma unroll
        for (int ks = 0; ks < AKT; ks += 8) {
            uint32_t a[4];
            a[0] = Ps[(r0    ) * AST + ks + cq    ];
            a[1] = Ps[(r0 + 8) * AST + ks + cq    ];
            a[2] = Ps[(r0    ) * AST + ks + cq + 4];
            a[3] = Ps[(r0 + 8) * AST + ks + cq + 4];
            #pragma unroll
            for (int j = 0; j < 8; j++) {
                uint32_t bfr[2];
                bfr[0] = Vs[(ks + cq    ) * AST + j * 8 + rsub];
                bfr[1] = Vs[(ks + cq + 4) * AST + j * 8 + rsub];
                mma_tf32(acc[j], a, bfr);
            }
        }
        __syncwarp();
    }

    // ---- write O ----
    const float inv0 = 1.f / l0;
    const float inv1 = 1.f / l1;
    const int q0g = qt * AQT + r0;
    #pragma unroll
    for (int j = 0; j < 8; j++) {
        int col = h * HD_ + j * 8 + cq * 2;
        float2 v0 = make_float2(acc[j][0] * inv0, acc[j][1] * inv0);
        float2 v1 = make_float2(acc[j][2] * inv1, acc[j][3] * inv1);
        *(float2*)&o[((size_t)b * S_ + q0g    ) * HDIM_ + col] = v0;
        *(float2*)&o[((size_t)b * S_ + q0g + 8) * HDIM_ + col] = v1;
    }
}

#define ATTN_SMEM_BYTES (((AQT + AKT + AKT + AQT) * AST + LREL_) * (int)sizeof(float))

// ---------------- host orchestration ----------------
extern "C" void kernel_launch(void* const* d_in, const int* in_sizes, int n_in,
                              void* d_out, int out_size) {
    const float* x        = (const float*)d_in[0];
    const float* pe_ln1_g = (const float*)d_in[1];
    const float* pe_ln1_b = (const float*)d_in[2];
    const float* pe_w     = (const float*)d_in[3];
    const float* pe_b     = (const float*)d_in[4];
    const float* pe_ln2_g = (const float*)d_in[5];
    const float* pe_ln2_b = (const float*)d_in[6];
    const float* lnA_g    = (const float*)d_in[7];
    const float* lnA_b    = (const float*)d_in[8];
    const float* qkv_w    = (const float*)d_in[9];
    const float* qkv_b    = (const float*)d_in[10];
    const float* out_w    = (const float*)d_in[11];
    const float* out_b    = (const float*)d_in[12];
    const float* lnF_g    = (const float*)d_in[13];
    const float* lnF_b    = (const float*)d_in[14];
    const float* fc1_w    = (const float*)d_in[15];
    const float* fc1_b    = (const float*)d_in[16];
    const float* fc2_w    = (const float*)d_in[17];
    const float* fc2_b    = (const float*)d_in[18];
    const float* rel_tab  = (const float*)d_in[19];
    const float* final_g  = (const float*)d_in[20];
    const float* final_b  = (const float*)d_in[21];
    const float* head_w   = (const float*)d_in[22];
    const float* head_b   = (const float*)d_in[23];
    float* out = (float*)d_out;

    float *zin, *z, *h, *qkv, *o, *f;
    cudaGetSymbolAddress((void**)&zin, g_zin);
    cudaGetSymbolAddress((void**)&z,   g_z);
    cudaGetSymbolAddress((void**)&h,   g_h);
    cudaGetSymbolAddress((void**)&qkv, g_qkv);
    cudaGetSymbolAddress((void**)&o,   g_o);
    cudaGetSymbolAddress((void**)&f,   g_f);

    cudaFuncSetAttribute(attn_mma,
                         cudaFuncAttributeMaxDynamicSharedMemorySize,
                         ATTN_SMEM_BYTES);
    cudaFuncSetAttribute(gemm_tf32<0>,
                         cudaFuncAttributeMaxDynamicSharedMemorySize,
                         GEMM_SMEM_BYTES);
    cudaFuncSetAttribute(gemm_tf32<1>,
                         cudaFuncAttributeMaxDynamicSharedMemorySize,
                         GEMM_SMEM_BYTES);
    cudaFuncSetAttribute(gemm_tf32<2>,
                         cudaFuncAttributeMaxDynamicSharedMemorySize,
                         GEMM_SMEM_BYTES);

    // patch embed: LN(1280) -> GEMM -> LN(1024)
    ln_kernel<<<ROWS_, 256>>>(x, pe_ln1_g, pe_ln1_b, zin, INDIM_, 1e-6f);
    gemm_tf32<0><<<dim3(HDIM_ / BN, ROWS_ / BM), 256, GEMM_SMEM_BYTES>>>(
        zin, pe_w, pe_b, nullptr, h, ROWS_, HDIM_, INDIM_);
    ln_kernel<<<ROWS_, 256>>>(h, pe_ln2_g, pe_ln2_b, z, HDIM_, 1e-6f);

    for (int l = 0; l < NL_; l++) {
        const float* qw = qkv_w + (size_t)l * 3 * HDIM_ * HDIM_;
        const float* qb = qkv_b + (size_t)l * 3 * HDIM_;
        const float* ow = out_w + (size_t)l * HDIM_ * HDIM_;
        const float* ob = out_b + (size_t)l * HDIM_;
        const float* f1w = fc1_w + (size_t)l * FF_ * HDIM_;
        const float* f1b = fc1_b + (size_t)l * FF_;
        const float* f2w = fc2_w + (size_t)l * HDIM_ * FF_;
        const float* f2b = fc2_b + (size_t)l * HDIM_;

        ln_kernel<<<ROWS_, 256>>>(z, lnA_g + l * HDIM_, lnA_b + l * HDIM_, h, HDIM_, 1e-5f);
        gemm_tf32<0><<<dim3(3 * HDIM_ / BN, ROWS_ / BM), 256, GEMM_SMEM_BYTES>>>(
            h, qw, qb, nullptr, qkv, ROWS_, 3 * HDIM_, HDIM_);
        attn_mma<<<dim3(S_ / AQT, B_ * NH_), 256, ATTN_SMEM_BYTES>>>(qkv, rel_tab, o);
        gemm_tf32<2><<<dim3(HDIM_ / BN, ROWS_ / BM), 256, GEMM_SMEM_BYTES>>>(
            o, ow, ob, z, z, ROWS_, HDIM_, HDIM_);
        ln_kernel<<<ROWS_, 256>>>(z, lnF_g + l * HDIM_, lnF_b + l * HDIM_, h, HDIM_, 1e-5f);
        gemm_tf32<1><<<dim3(FF_ / BN, ROWS_ / BM), 256, GEMM_SMEM_BYTES>>>(
            h, f1w, f1b, nullptr, f, ROWS_, FF_, HDIM_);
        gemm_tf32<2><<<dim3(HDIM_ / BN, ROWS_ / BM), 256, GEMM_SMEM_BYTES>>>(
            f, f2w, f2b, z, z, ROWS_, HDIM_, FF_);
    }

    ln_kernel<<<ROWS_, 256>>>(z, final_g, final_b, h, HDIM_, 1e-5f);
    gemm_tf32<0><<<dim3((NCLS_ + BN - 1) / BN, ROWS_ / BM), 256, GEMM_SMEM_BYTES>>>(
        h, head_w, head_b, nullptr, out, ROWS_, NCLS_, HDIM_);
}